// round 5
// baseline (speedup 1.0000x reference)
#include <cuda_runtime.h>
#include <cstdint>

// Problem constants
#define MAX_DIST 35.0f
#define BOX 71            // ceil(2*35/1 + 1)
#define FDIM 32
#define BATCH 8
#define NPTS 16384

// Derived sizes (in float4 units)
#define SLICE0_F4 (BOX * BOX * BOX * FDIM / 4)          // 2,863,288
#define TOTAL_F4  (BATCH * BOX * BOX * BOX * FDIM / 4)  // 22,906,304
#define SCATTER_WORK (BATCH * NPTS * (FDIM / 4))        // 1,048,576 point-quads

// One resident wave: 6 CTAs/SM x 148 SMs (guaranteed by __launch_bounds__).
#define NB 888
#define BLOCK 256
#define NT (NB * BLOCK)                                  // 227,328 threads

// Grid-barrier state. g_count self-resets to 0 within each launch;
// g_gen grows monotonically across graph replays (works for any start value).
__device__ unsigned g_count = 0;
__device__ unsigned g_gen = 0;

// ---------------------------------------------------------------------------
// Single persistent kernel:
//   Phase 1: zero batch slice 0 with PLAIN stores (keeps the 45.8 MB region
//            L2-resident so the scatter atomics are L2 hits).
//   Grid barrier (sense-reversing; all NB blocks co-resident -> safe).
//   Phase 2: interleaved scatter + streaming-zero of slices 1..7 (320 MB,
//            __stcs evict-first: write-only data, keep L2 for atomics).
// Scatter semantics (faithful to the reference):
//   - ALL B*N points land in batch slice 0 (reference's tf.zeros batch column)
//   - round-half-to-even via __float2int_rn (jnp.round)
//   - out-of-box points contribute exactly +0.0 -> skipped
//   - red.global.add.v4.f32: fire-and-forget vector reduction (REDG @ L2)
// ---------------------------------------------------------------------------
__global__ void __launch_bounds__(BLOCK, 6)
fused_all_kernel(const float* __restrict__ coords,
                 const float4* __restrict__ feats,
                 float* __restrict__ out)
{
    const int t = blockIdx.x * BLOCK + threadIdx.x;
    float4* out4 = (float4*)out;
    const float4 z = make_float4(0.f, 0.f, 0.f, 0.f);

    // ---- Phase 1: zero slice 0 (plain stores -> L2 resident) ----
    for (int i = t; i < SLICE0_F4; i += NT)
        out4[i] = z;

    // ---- Grid barrier ----
    __threadfence();          // release phase-1 stores to L2/coherent point
    __syncthreads();
    if (threadIdx.x == 0) {
        unsigned my_gen = *(volatile unsigned*)&g_gen;  // read before arriving
        if (atomicAdd(&g_count, 1) == NB - 1) {
            g_count = 0;                 // reset for next replay
            __threadfence();
            atomicAdd(&g_gen, 1);        // release all spinners
        } else {
            while (*(volatile unsigned*)&g_gen == my_gen)
                __nanosleep(64);
        }
    }
    __syncthreads();

    // ---- Phase 2: interleaved scatter + zero slices 1..7 ----
    long long i = (long long)SLICE0_F4 + t;
    int w = t;
    #pragma unroll 1
    while (w < SCATTER_WORK) {
        int p = w >> 3;          // global point index (b*N + n)
        int q = w & 7;           // which float4 of the 8 covering F=32

        // Issue scatter inputs; latency hides under the zero stores below.
        float c0 = __ldg(&coords[p * 3 + 0]);
        float c1 = __ldg(&coords[p * 3 + 1]);
        float c2 = __ldg(&coords[p * 3 + 2]);
        float4 v = __ldg(&feats[(long long)p * 8 + q]);

        #pragma unroll
        for (int k = 0; k < 18; k++) {
            if (i < TOTAL_F4) { __stcs(&out4[i], z); }
            i += NT;
        }

        int g0 = __float2int_rn(c0 + MAX_DIST);
        int g1 = __float2int_rn(c1 + MAX_DIST);
        int g2 = __float2int_rn(c2 + MAX_DIST);
        if ((unsigned)g0 < BOX && (unsigned)g1 < BOX && (unsigned)g2 < BOX) {
            int cell = (g0 * BOX + g1) * BOX + g2;
            float* dst = out + (long long)cell * FDIM + q * 4;   // slice 0
            asm volatile("red.global.add.v4.f32 [%0], {%1, %2, %3, %4};"
                         :: "l"(dst), "f"(v.x), "f"(v.y), "f"(v.z), "f"(v.w)
                         : "memory");
        }
        w += NT;
    }
    // Drain remaining zero stores.
    for (; i < TOTAL_F4; i += NT)
        __stcs(&out4[i], z);
}

extern "C" void kernel_launch(void* const* d_in, const int* in_sizes, int n_in,
                              void* d_out, int out_size) {
    const float* coords = (const float*)d_in[0];     // [8,16384,3] f32
    const float4* feats = (const float4*)d_in[1];    // [8,16384,32] f32 as float4
    float* out = (float*)d_out;                      // [8,71,71,71,32] f32

    fused_all_kernel<<<NB, BLOCK>>>(coords, feats, out);
}

// round 6
// speedup vs baseline: 1.0916x; 1.0916x over previous
#include <cuda_runtime.h>
#include <cstdint>

// Problem constants
#define MAX_DIST 35.0f
#define BOX 71            // ceil(2*35/1 + 1)
#define FDIM 32
#define BATCH 8
#define NPTS 16384

// Derived sizes (in float4 units)
#define SLICE0_F4 (BOX * BOX * BOX * FDIM / 4)          // 2,863,288
#define TOTAL_F4  (BATCH * BOX * BOX * BOX * FDIM / 4)  // 22,906,304
#define SCATTER_WORK (BATCH * NPTS * (FDIM / 4))        // 1,048,576 point-quads
#define NTHREADS SCATTER_WORK                           // 1 scatter item / thread

// ---------------------------------------------------------------------------
// Kernel A: zero batch slice 0 (45.8 MB) with PLAIN stores.
// Write-allocate keeps the region L2-resident (45.8 MB << 126 MB L2), so:
//   - the stores commit at L2 rate, not DRAM rate,
//   - kernel B's red.global.add atomics become L2 hits (no DRAM RMW),
//   - the single obligatory DRAM writeback happens lazily during kernel B.
// ---------------------------------------------------------------------------
__global__ void __launch_bounds__(256)
zero_slice0_kernel(float4* __restrict__ out) {
    int i = blockIdx.x * blockDim.x + threadIdx.x;
    int stride = gridDim.x * blockDim.x;
    const float4 z = make_float4(0.f, 0.f, 0.f, 0.f);
    for (; i < SLICE0_F4; i += stride) {
        out[i] = z;                    // plain store: L2 write-allocate
    }
}

// ---------------------------------------------------------------------------
// Kernel B (fused, R4-proven shape): 1,048,576 threads (4096 x 256).
//   Each thread:
//     1. issues its scatter input loads (coords + feature quad) up front,
//     2. streams zeros into slices 1..7 (__stcs evict-first: write-only
//        data, keeps L2 reserved for the slice-0 working set),
//     3. fires one red.global.add.v4.f32 into batch slice 0 mid-stream,
//     4. finishes its zero stripe.
// Scatter semantics (faithful to the reference):
//   - ALL B*N points land in batch slice 0 (reference's tf.zeros batch column)
//   - round-half-to-even via __float2int_rn (jnp.round)
//   - out-of-box points contribute exactly +0.0 -> skipped
// ---------------------------------------------------------------------------
__global__ void __launch_bounds__(256)
fused_scatter_zero_kernel(const float* __restrict__ coords,
                          const float4* __restrict__ features4,
                          float* __restrict__ out) {
    const int tid = blockIdx.x * blockDim.x + threadIdx.x;

    const int p = tid >> 3;        // global point index (b*N + n)
    const int q = tid & 7;         // which float4 of the 8 covering F=32

    // Issue all scatter inputs NOW; consumed after 6 store batches so the
    // DRAM latency hides under the streaming stores.
    float c0 = __ldg(&coords[p * 3 + 0]);
    float c1 = __ldg(&coords[p * 3 + 1]);
    float c2 = __ldg(&coords[p * 3 + 2]);
    float4 v = __ldg(&features4[(long long)p * 8 + q]);

    float4* out4 = (float4*)out;
    const float4 z = make_float4(0.f, 0.f, 0.f, 0.f);

    long long i = (long long)SLICE0_F4 + tid;

    #pragma unroll
    for (int k = 0; k < 6; k++) {
        if (i < TOTAL_F4) { __stcs(&out4[i], z); }
        i += NTHREADS;
    }

    // Scatter: loads have landed; fire-and-forget vector reduction (L2 hit).
    {
        int g0 = __float2int_rn(c0 + MAX_DIST);
        int g1 = __float2int_rn(c1 + MAX_DIST);
        int g2 = __float2int_rn(c2 + MAX_DIST);
        if ((unsigned)g0 < BOX && (unsigned)g1 < BOX && (unsigned)g2 < BOX) {
            int cell = (g0 * BOX + g1) * BOX + g2;
            float* dst = out + (long long)cell * FDIM + q * 4;  // slice 0
            asm volatile("red.global.add.v4.f32 [%0], {%1, %2, %3, %4};"
                         :: "l"(dst), "f"(v.x), "f"(v.y), "f"(v.z), "f"(v.w)
                         : "memory");
        }
    }

    // Remaining zero stores.
    for (; i < TOTAL_F4; i += NTHREADS) {
        __stcs(&out4[i], z);
    }
}

extern "C" void kernel_launch(void* const* d_in, const int* in_sizes, int n_in,
                              void* d_out, int out_size) {
    const float* coords = (const float*)d_in[0];     // [8,16384,3] f32
    const float4* feats = (const float4*)d_in[1];    // [8,16384,32] f32 as float4
    float* out = (float*)d_out;                      // [8,71,71,71,32] f32

    // Kernel A: zero slice 0, L2-resident (ordering dep for the atomics).
    zero_slice0_kernel<<<148 * 8, 256>>>((float4*)out);

    // Kernel B: fused scatter + zero of slices 1..7.
    fused_scatter_zero_kernel<<<SCATTER_WORK / 256, 256>>>(coords, feats, out);
}